// round 7
// baseline (speedup 1.0000x reference)
#include <cuda_runtime.h>
#include <cuda_bf16.h>
#include <cstdint>

#define B_  4
#define L_  1024
#define H_  1024
#define NH_ 16
#define HD_ 64
#define M_  (B_*L_)   // 4096
#define LOG2E 1.4426950408889634f

// ---------------- scratch ----------------
__device__ float g_Q  [M_ * H_];
__device__ float g_KVs[M_ * 2 * H_];
__device__ float g_KVl[M_ * 2 * H_];
__device__ float g_Vts[B_ * NH_ * HD_ * L_];
__device__ float g_Vtl[B_ * NH_ * HD_ * L_];
__device__ float g_mix[M_ * H_];
__device__ float g_xr [M_ * H_];
__device__ float g_Wqt[H_ * H_];
__device__ float g_Wst[2 * H_ * H_];
__device__ float g_Wlt[2 * H_ * H_];
__device__ float g_Wot[H_ * H_];

// ---------------- PTX helpers ----------------
__device__ __forceinline__ unsigned f2tf(float x) {
    unsigned u; asm("cvt.rna.tf32.f32 %0, %1;" : "=r"(u) : "f"(x)); return u;
}
__device__ __forceinline__ float f2tff(float x) { return __uint_as_float(f2tf(x)); }
__device__ __forceinline__ float ex2(float x) {
    float y; asm("ex2.approx.ftz.f32 %0, %1;" : "=f"(y) : "f"(x)); return y;
}
__device__ __forceinline__ void mma8(float* d,
                                     const unsigned* a, unsigned b0, unsigned b1) {
    asm volatile(
        "mma.sync.aligned.m16n8k8.row.col.f32.tf32.tf32.f32 "
        "{%0,%1,%2,%3}, {%4,%5,%6,%7}, {%8,%9}, {%0,%1,%2,%3};"
        : "+f"(d[0]), "+f"(d[1]), "+f"(d[2]), "+f"(d[3])
        : "r"(a[0]), "r"(a[1]), "r"(a[2]), "r"(a[3]), "r"(b0), "r"(b1));
}
__device__ __forceinline__ void ldsm4(uint32_t* r, uint32_t addr) {
    asm volatile("ldmatrix.sync.aligned.m8n8.x4.shared.b16 {%0,%1,%2,%3}, [%4];"
        : "=r"(r[0]), "=r"(r[1]), "=r"(r[2]), "=r"(r[3]) : "r"(addr));
}
__device__ __forceinline__ void cp16(void* smem_dst, const void* gmem_src) {
    unsigned s = (unsigned)__cvta_generic_to_shared(smem_dst);
    asm volatile("cp.async.cg.shared.global [%0], [%1], 16;" :: "r"(s), "l"(gmem_src));
}
__device__ __forceinline__ uint32_t smem_u32(const void* p) {
    uint32_t a;
    asm("{ .reg .u64 t; cvta.to.shared.u64 t, %1; cvt.u32.u64 %0, t; }" : "=r"(a) : "l"(p));
    return a;
}
#define GSW(o) ((o) ^ (((o) >> 3) & 0x70))

// ---------------- preprocessing ----------------
__global__ __launch_bounds__(256) void round_tf32(
    const float* __restrict__ src, float* __restrict__ dst, int n4)
{
    int i = blockIdx.x * blockDim.x + threadIdx.x;
    if (i >= n4) return;
    float4 v = ((const float4*)src)[i];
    v.x = f2tff(v.x); v.y = f2tff(v.y); v.z = f2tff(v.z); v.w = f2tff(v.w);
    ((float4*)dst)[i] = v;
}

__global__ __launch_bounds__(256) void wtrans(
    const float* __restrict__ Wq, const float* __restrict__ Ws,
    const float* __restrict__ Wl, const float* __restrict__ Wo,
    float* __restrict__ Tq, float* __restrict__ Ts,
    float* __restrict__ Tl, float* __restrict__ To)
{
    const int z = blockIdx.z;
    const float* W = (z == 0) ? Wq : (z == 1) ? Ws : (z == 2) ? Wl : Wo;
    float* T = (z == 0) ? Tq : (z == 1) ? Ts : (z == 2) ? Tl : To;
    const int N = (z == 1 || z == 2) ? 2 * H_ : H_;
    const int n0 = blockIdx.x * 32, k0 = blockIdx.y * 32;
    if (n0 >= N) return;
    __shared__ float ts[32][33];
    const int tx = threadIdx.x, ty = threadIdx.y;
#pragma unroll
    for (int i = 0; i < 4; i++)
        ts[ty + 8 * i][tx] = W[(size_t)(k0 + ty + 8 * i) * N + n0 + tx];
    __syncthreads();
#pragma unroll
    for (int i = 0; i < 4; i++)
        T[(size_t)(n0 + ty + 8 * i) * H_ + k0 + tx] = f2tff(ts[tx][ty + 8 * i]);
}

__global__ __launch_bounds__(256) void vtrans(
    const float* __restrict__ KVs, const float* __restrict__ KVl,
    float* __restrict__ Vts, float* __restrict__ Vtl)
{
    const int z = blockIdx.z;
    const int branch = z >> 6, bh = z & 63;
    const int b = bh >> 4, h = bh & 15;
    const float* KV = branch ? KVl : KVs;
    float* Vt = branch ? Vtl : Vts;
    __shared__ float ts[32][33];
    const int l0 = blockIdx.x * 32, d0 = blockIdx.y * 32;
    const int tx = threadIdx.x, ty = threadIdx.y;
#pragma unroll
    for (int i = 0; i < 4; i++)
        ts[ty + 8 * i][tx] =
            KV[(size_t)(b * L_ + l0 + ty + 8 * i) * (2 * H_) + H_ + h * HD_ + d0 + tx];
    __syncthreads();
#pragma unroll
    for (int i = 0; i < 4; i++)
        Vt[((size_t)(bh * HD_ + d0 + ty + 8 * i)) * L_ + l0 + tx] = ts[tx][ty + 8 * i];
}

// ---------------- tf32 GEMM: 4 warps, warp tile 64x64, 3-stage ----------------
#define GSTG 32768                 // A 16KB + B 16KB per stage
#define GS_SMEM (3 * GSTG)         // 98304

__global__ __launch_bounds__(128, 2) void gemm_tf32v(
    const float* __restrict__ A, const float* __restrict__ Bm,
    float* __restrict__ C, int M, int N, int K, int roundOut)
{
    extern __shared__ char smem[];
    const uint32_t sb = smem_u32(smem);
    const int tid = threadIdx.x, lane = tid & 31, wid = tid >> 5;
    const int bm = blockIdx.y * 128, bn = blockIdx.x * 128;
    const int wm = (wid & 1) * 64, wn = (wid >> 1) * 64;

    // load mapping: 1 thread per row, 8 chunks of 16B
    const float* Ag = A + (size_t)(bm + tid) * K;
    const float* Bg = Bm + (size_t)(bn + tid) * K;
    uint32_t sdst[8];
#pragma unroll
    for (int c = 0; c < 8; c++) sdst[c] = GSW(tid * 128 + c * 16);

    const int lm = lane >> 3, lr = lane & 7;
    const uint32_t aRow = wm + (lm & 1) * 8 + lr;
    const uint32_t aKh  = (lm >> 1) * 16;
    const uint32_t bRow = wn + (lm >> 1) * 8 + lr;
    const uint32_t bKh  = (lm & 1) * 16;

    float acc[4][8][4];
#pragma unroll
    for (int i = 0; i < 4; i++)
#pragma unroll
        for (int j = 0; j < 8; j++)
#pragma unroll
            for (int r = 0; r < 4; r++) acc[i][j][r] = 0.0f;

    const int NT = K / 32;

    // prologue: stages 0,1
#pragma unroll
    for (int s = 0; s < 2; s++) {
        char* sd = smem + s * GSTG;
        const int k0 = s * 32;
#pragma unroll
        for (int c = 0; c < 8; c++) {
            cp16(sd + sdst[c], Ag + k0 + c * 4);
            cp16(sd + 16384 + sdst[c], Bg + k0 + c * 4);
        }
        asm volatile("cp.async.commit_group;");
    }

    int stage = 0;
    for (int t = 0; t < NT; t++) {
        asm volatile("cp.async.wait_group 1;");
        __syncthreads();
        if (t + 2 < NT) {
            char* sd = smem + ((stage + 2) % 3) * GSTG;
            const int k0 = (t + 2) * 32;
#pragma unroll
            for (int c = 0; c < 8; c++) {
                cp16(sd + sdst[c], Ag + k0 + c * 4);
                cp16(sd + 16384 + sdst[c], Bg + k0 + c * 4);
            }
            asm volatile("cp.async.commit_group;");
        }

        const uint32_t sA = sb + stage * GSTG;
        const uint32_t sB = sA + 16384;
#pragma unroll
        for (int ks = 0; ks < 4; ks++) {
            uint32_t af[4][4], bf[4][4];
#pragma unroll
            for (int im = 0; im < 4; im++)
                ldsm4(af[im], sA + GSW((aRow + im * 16) * 128 + ks * 32 + aKh));
#pragma unroll
            for (int jp = 0; jp < 4; jp++)
                ldsm4(bf[jp], sB + GSW((bRow + jp * 16) * 128 + ks * 32 + bKh));
#pragma unroll
            for (int im = 0; im < 4; im++)
#pragma unroll
                for (int jn = 0; jn < 8; jn++) {
                    const uint32_t* bb = bf[jn >> 1];
                    const int s = (jn & 1) * 2;
                    mma8(acc[im][jn], af[im], bb[s], bb[s + 1]);
                }
        }
        stage = (stage + 1) % 3;
    }

    const int er = lane >> 2, ec = 2 * (lane & 3);
#pragma unroll
    for (int im = 0; im < 4; im++)
#pragma unroll
        for (int jn = 0; jn < 8; jn++) {
            const int row = bm + wm + im * 16 + er;
            const int col = bn + wn + jn * 8 + ec;
            float v0 = acc[im][jn][0], v1 = acc[im][jn][1];
            float v2 = acc[im][jn][2], v3 = acc[im][jn][3];
            if (roundOut) { v0 = f2tff(v0); v1 = f2tff(v1); v2 = f2tff(v2); v3 = f2tff(v3); }
            *(float2*)&C[(size_t)row * N + col] = make_float2(v0, v1);
            *(float2*)&C[(size_t)(row + 8) * N + col] = make_float2(v2, v3);
        }
}

// ---------------- dual-branch flash attention: 8 warps x 32 q-rows ----------------
#define ATK 17408
#define ASTG 34816
#define AT_P 69632
#define ATTN_SMEM (AT_P + 256 * 272)   // 139264

__global__ __launch_bounds__(256, 1) void attn_mma(
    const float* __restrict__ Q, const float* __restrict__ KVs,
    const float* __restrict__ KVl, const float* __restrict__ Vts,
    const float* __restrict__ Vtl, float* __restrict__ Out,
    const float* __restrict__ p_mixw, const float* __restrict__ p_decay)
{
    extern __shared__ char smem[];
    const uint32_t sb = smem_u32(smem);
    const int tid = threadIdx.x, lane = tid & 31, wid = tid >> 5;
    const int g = lane >> 2, tg = lane & 3;
    const int q0 = blockIdx.x * 256;
    const int h = blockIdx.y, b = blockIdx.z;
    const int bh = b * NH_ + h;
    const int mw = wid * 32;

    const float alpha   = 1.0f / (1.0f + __expf(-p_mixw[0]));
    const float lambda2 = (1.0f - p_decay[0]) * LOG2E;
    const float wmix[2] = {alpha, 1.0f - alpha};
    const float QSCALE  = 0.125f * LOG2E;

    const int lm = lane >> 3, lr = lane & 7;
    const uint32_t bRow = (uint32_t)((lm >> 1) * 8 + lr);
    const uint32_t bKh  = (uint32_t)((lm & 1) * 16);
    const uint32_t pRow = (uint32_t)(mw + (lm & 1) * 8 + lr);
    const uint32_t pKh  = (uint32_t)((lm >> 1) * 16);

    // Q fragments in registers: 2 m-tiles x 8 ks
    unsigned qa[8][2][4];
#pragma unroll
    for (int im = 0; im < 2; im++) {
        const float* rA = Q + ((size_t)(b * L_ + q0 + mw + im * 16 + g)) * H_ + h * HD_;
        const float* rB = rA + (size_t)8 * H_;
#pragma unroll
        for (int ks = 0; ks < 8; ks++) {
            const int d0 = ks * 8 + tg;
            qa[ks][im][0] = f2tf(rA[d0] * QSCALE);
            qa[ks][im][1] = f2tf(rB[d0] * QSCALE);
            qa[ks][im][2] = f2tf(rA[d0 + 4] * QSCALE);
            qa[ks][im][3] = f2tf(rB[d0 + 4] * QSCALE);
        }
    }

    const int kr = tid >> 2, c0 = tid & 3;

    auto issue_load = [&](int slot) {
        const int br = slot >> 4, tt = slot & 15;
        const float* Kb = (br ? KVl : KVs) +
            ((size_t)(b * L_ + tt * 64 + kr)) * (2 * H_) + h * HD_;
        const float* Vb = (br ? Vtl : Vts) +
            ((size_t)(bh * HD_ + kr)) * L_ + tt * 64;
        char* stg = smem + (slot & 1) * ASTG;
        char* krow_s = stg + kr * 272;
        char* vrow_s = stg + ATK + kr * 272;
#pragma unroll
        for (int c = 0; c < 4; c++) {
            const int ch = c0 + c * 4;
            cp16(krow_s + ch * 16, Kb + ch * 4);
            cp16(vrow_s + ch * 16, Vb + ch * 4);
        }
        asm volatile("cp.async.commit_group;");
    };

    issue_load(0);

    for (int branch = 0; branch < 2; branch++) {
        float lsum[2][2] = {{0.0f, 0.0f}, {0.0f, 0.0f}};
        float o[2][8][4];
#pragma unroll
        for (int im = 0; im < 2; im++)
#pragma unroll
            for (int jn = 0; jn < 8; jn++)
#pragma unroll
                for (int r = 0; r < 4; r++) o[im][jn][r] = 0.0f;

        for (int t = 0; t < 16; t++) {
            const int slot = branch * 16 + t;
            asm volatile("cp.async.wait_group 0;");
            __syncthreads();
            if (slot + 1 < 32) issue_load(slot + 1);

            const uint32_t stK = sb + (slot & 1) * ASTG;
            const uint32_t stV = stK + ATK;

            // ---- S = Q K^T ----
            float s[2][8][4];
#pragma unroll
            for (int im = 0; im < 2; im++)
#pragma unroll
                for (int jn = 0; jn < 8; jn++)
#pragma unroll
                    for (int r = 0; r < 4; r++) s[im][jn][r] = 0.0f;
#pragma unroll
            for (int ks = 0; ks < 8; ks++) {
                uint32_t bf[4][4];
#pragma unroll
                for (int jp = 0; jp < 4; jp++)
                    ldsm4(bf[jp], stK + (bRow + jp * 16) * 272 + ks * 32 + bKh);
#pragma unroll
                for (int im = 0; im < 2; im++)
#pragma unroll
                    for (int jn = 0; jn < 8; jn++) {
                        const uint32_t* bb = bf[jn >> 1];
                        const int sx = (jn & 1) * 2;
                        mma8(s[im][jn], qa[ks][im], bb[sx], bb[sx + 1]);
                    }
            }

            if (branch == 0) {
#pragma unroll
                for (int im = 0; im < 2; im++) {
                    const float r0 = (float)(q0 + mw + im * 16 + g), r1 = r0 + 8.0f;
#pragma unroll
                    for (int jn = 0; jn < 8; jn++) {
                        const float cA = (float)(t * 64 + jn * 8 + 2 * tg), cB = cA + 1.0f;
                        s[im][jn][0] -= fabsf(r0 - cA) * lambda2;
                        s[im][jn][1] -= fabsf(r0 - cB) * lambda2;
                        s[im][jn][2] -= fabsf(r1 - cA) * lambda2;
                        s[im][jn][3] -= fabsf(r1 - cB) * lambda2;
                    }
                }
            }

            // ---- p = exp2(s - 12); lane-local l; store P ----
#pragma unroll
            for (int im = 0; im < 2; im++) {
                float* pd = (float*)(smem + AT_P + (mw + im * 16 + g) * 272);
#pragma unroll
                for (int jn = 0; jn < 8; jn++) {
                    const int col = jn * 8 + 2 * tg;
                    const float p0 = ex2(s[im][jn][0] - 12.0f);
                    const float p1 = ex2(s[im][jn][1] - 12.0f);
                    const float p2 = ex2(s[im][jn][2] - 12.0f);
                    const float p3 = ex2(s[im][jn][3] - 12.0f);
                    lsum[im][0] += p0 + p1; lsum[im][1] += p2 + p3;
                    *(float2*)(pd + col) = make_float2(f2tff(p0), f2tff(p1));
                    *(float2*)(pd + 8 * 68 + col) = make_float2(f2tff(p2), f2tff(p3));
                }
            }
            __syncwarp();

            // ---- O += P V ----
#pragma unroll
            for (int ks = 0; ks < 8; ks++) {
                uint32_t pf[2][4], vf[4][4];
#pragma unroll
                for (int im = 0; im < 2; im++)
                    ldsm4(pf[im], sb + AT_P + (pRow + im * 16) * 272 + ks * 32 + pKh);
#pragma unroll
                for (int jp = 0; jp < 4; jp++)
                    ldsm4(vf[jp], stV + (bRow + jp * 16) * 272 + ks * 32 + bKh);
#pragma unroll
                for (int im = 0; im < 2; im++)
#pragma unroll
                    for (int jn = 0; jn < 8; jn++) {
                        const uint32_t* bb = vf[jn >> 1];
                        const int sx = (jn & 1) * 2;
                        mma8(o[im][jn], pf[im], bb[sx], bb[sx + 1]);
                    }
            }
        }

#pragma unroll
        for (int im = 0; im < 2; im++) {
            lsum[im][0] += __shfl_xor_sync(0xffffffffu, lsum[im][0], 1);
            lsum[im][0] += __shfl_xor_sync(0xffffffffu, lsum[im][0], 2);
            lsum[im][1] += __shfl_xor_sync(0xffffffffu, lsum[im][1], 1);
            lsum[im][1] += __shfl_xor_sync(0xffffffffu, lsum[im][1], 2);
        }

        const float w = wmix[branch];
#pragma unroll
        for (int im = 0; im < 2; im++) {
            const float i0 = w / lsum[im][0], i1 = w / lsum[im][1];
            float* ob = Out + ((size_t)(b * L_ + q0 + mw + im * 16 + g)) * H_ + h * HD_;
            if (branch == 0) {
#pragma unroll
                for (int jn = 0; jn < 8; jn++) {
                    const int col = jn * 8 + 2 * tg;
                    *(float2*)(ob + col) = make_float2(o[im][jn][0] * i0, o[im][jn][1] * i0);
                    *(float2*)(ob + 8 * H_ + col) = make_float2(o[im][jn][2] * i1, o[im][jn][3] * i1);
                }
            } else {
#pragma unroll
                for (int jn = 0; jn < 8; jn++) {
                    const int col = jn * 8 + 2 * tg;
                    float2 u0 = *(float2*)(ob + col);
                    float2 u1 = *(float2*)(ob + 8 * H_ + col);
                    *(float2*)(ob + col) =
                        make_float2(f2tff(u0.x + o[im][jn][0] * i0), f2tff(u0.y + o[im][jn][1] * i0));
                    *(float2*)(ob + 8 * H_ + col) =
                        make_float2(f2tff(u1.x + o[im][jn][2] * i1), f2tff(u1.y + o[im][jn][3] * i1));
                }
            }
        }
    }
}

// ---------------------------------------------------------------------------
extern "C" void kernel_launch(void* const* d_in, const int* in_sizes, int n_in,
                              void* d_out, int out_size)
{
    const float* x     = (const float*)d_in[0];
    const float* Wq    = (const float*)d_in[1];
    const float* Wkvs  = (const float*)d_in[2];
    const float* Wkvl  = (const float*)d_in[3];
    const float* Wo    = (const float*)d_in[4];
    const float* mixw  = (const float*)d_in[5];
    const float* decay = (const float*)d_in[6];
    float* out = (float*)d_out;

    float *pQ, *pKVs, *pKVl, *pVts, *pVtl, *pmix, *pxr, *pwq, *pws, *pwl, *pwo;
    cudaGetSymbolAddress((void**)&pQ,   g_Q);
    cudaGetSymbolAddress((void**)&pKVs, g_KVs);
    cudaGetSymbolAddress((void**)&pKVl, g_KVl);
    cudaGetSymbolAddress((void**)&pVts, g_Vts);
    cudaGetSymbolAddress((void**)&pVtl, g_Vtl);
    cudaGetSymbolAddress((void**)&pmix, g_mix);
    cudaGetSymbolAddress((void**)&pxr,  g_xr);
    cudaGetSymbolAddress((void**)&pwq,  g_Wqt);
    cudaGetSymbolAddress((void**)&pws,  g_Wst);
    cudaGetSymbolAddress((void**)&pwl,  g_Wlt);
    cudaGetSymbolAddress((void**)&pwo,  g_Wot);

    cudaFuncSetAttribute(gemm_tf32v,
                         cudaFuncAttributeMaxDynamicSharedMemorySize, GS_SMEM);
    cudaFuncSetAttribute(attn_mma,
                         cudaFuncAttributeMaxDynamicSharedMemorySize, ATTN_SMEM);

    // preprocess
    round_tf32<<<M_ * H_ / 4 / 256, 256>>>(x, pxr, M_ * H_ / 4);
    wtrans<<<dim3(2 * H_ / 32, H_ / 32, 4), dim3(32, 8)>>>(Wq, Wkvs, Wkvl, Wo,
                                                           pwq, pws, pwl, pwo);

    // projections
    gemm_tf32v<<<dim3(H_ / 128,     M_ / 128), 128, GS_SMEM>>>(pxr, pwq, pQ,   M_, H_,     H_, 1);
    gemm_tf32v<<<dim3(2 * H_ / 128, M_ / 128), 128, GS_SMEM>>>(pxr, pws, pKVs, M_, 2 * H_, H_, 1);
    gemm_tf32v<<<dim3(2 * H_ / 128, M_ / 128), 128, GS_SMEM>>>(pxr, pwl, pKVl, M_, 2 * H_, H_, 1);

    // V^T
    vtrans<<<dim3(L_ / 32, HD_ / 32, 128), dim3(32, 8)>>>(pKVs, pKVl, pVts, pVtl);

    // attention
    attn_mma<<<dim3(L_ / 256, NH_, B_), 256, ATTN_SMEM>>>(pQ, pKVs, pKVl, pVts, pVtl,
                                                          pmix, mixw, decay);

    // output projection
    gemm_tf32v<<<dim3(H_ / 128, M_ / 128), 128, GS_SMEM>>>(pmix, pwo, out, M_, H_, H_, 0);
}

// round 8
// speedup vs baseline: 2.3381x; 2.3381x over previous
#include <cuda_runtime.h>
#include <cuda_fp16.h>
#include <cstdint>

#define B_  4
#define L_  1024
#define H_  1024
#define NH_ 16
#define HD_ 64
#define M_  (B_*L_)   // 4096
#define LOG2E 1.4426950408889634f

// ---------------- scratch ----------------
__device__ __half g_xh [M_ * H_];
__device__ __half g_Qh [M_ * H_];        // pre-scaled by 0.125*log2e
__device__ __half g_KVsh[M_ * 2 * H_];
__device__ __half g_KVlh[M_ * 2 * H_];
__device__ __half g_mixh[M_ * H_];
__device__ __half g_Wqth[H_ * H_];
__device__ __half g_Wsth[2 * H_ * H_];
__device__ __half g_Wlth[2 * H_ * H_];
__device__ __half g_Woth[H_ * H_];

// ---------------- PTX helpers ----------------
__device__ __forceinline__ float ex2(float x) {
    float y; asm("ex2.approx.ftz.f32 %0, %1;" : "=f"(y) : "f"(x)); return y;
}
__device__ __forceinline__ void mma_f16(float* d, const uint32_t* a,
                                        uint32_t b0, uint32_t b1) {
    asm volatile(
        "mma.sync.aligned.m16n8k16.row.col.f32.f16.f16.f32 "
        "{%0,%1,%2,%3}, {%4,%5,%6,%7}, {%8,%9}, {%0,%1,%2,%3};"
        : "+f"(d[0]), "+f"(d[1]), "+f"(d[2]), "+f"(d[3])
        : "r"(a[0]), "r"(a[1]), "r"(a[2]), "r"(a[3]), "r"(b0), "r"(b1));
}
__device__ __forceinline__ void ldsm4(uint32_t* r, uint32_t addr) {
    asm volatile("ldmatrix.sync.aligned.m8n8.x4.shared.b16 {%0,%1,%2,%3}, [%4];"
        : "=r"(r[0]), "=r"(r[1]), "=r"(r[2]), "=r"(r[3]) : "r"(addr));
}
__device__ __forceinline__ void ldsm4t(uint32_t* r, uint32_t addr) {
    asm volatile("ldmatrix.sync.aligned.m8n8.x4.trans.shared.b16 {%0,%1,%2,%3}, [%4];"
        : "=r"(r[0]), "=r"(r[1]), "=r"(r[2]), "=r"(r[3]) : "r"(addr));
}
__device__ __forceinline__ void cp16(void* smem_dst, const void* gmem_src) {
    unsigned s = (unsigned)__cvta_generic_to_shared(smem_dst);
    asm volatile("cp.async.cg.shared.global [%0], [%1], 16;" :: "r"(s), "l"(gmem_src));
}
__device__ __forceinline__ uint32_t smem_u32(const void* p) {
    uint32_t a;
    asm("{ .reg .u64 t; cvta.to.shared.u64 t, %1; cvt.u32.u64 %0, t; }" : "=r"(a) : "l"(p));
    return a;
}
#define GSW(o) ((o) ^ (((o) >> 3) & 0x70))

// ---------------- preprocessing ----------------
__global__ __launch_bounds__(256) void to_half(
    const float* __restrict__ src, __half* __restrict__ dst, int n4)
{
    int i = blockIdx.x * blockDim.x + threadIdx.x;
    if (i >= n4) return;
    float4 v = ((const float4*)src)[i];
    ((__half2*)dst)[2 * i]     = __floats2half2_rn(v.x, v.y);
    ((__half2*)dst)[2 * i + 1] = __floats2half2_rn(v.z, v.w);
}

// W[K,N] fp32 -> Wt[N,K] half
__global__ __launch_bounds__(256) void wtrans_h(
    const float* __restrict__ Wq, const float* __restrict__ Ws,
    const float* __restrict__ Wl, const float* __restrict__ Wo,
    __half* __restrict__ Tq, __half* __restrict__ Ts,
    __half* __restrict__ Tl, __half* __restrict__ To)
{
    const int z = blockIdx.z;
    const float* W = (z == 0) ? Wq : (z == 1) ? Ws : (z == 2) ? Wl : Wo;
    __half* T = (z == 0) ? Tq : (z == 1) ? Ts : (z == 2) ? Tl : To;
    const int N = (z == 1 || z == 2) ? 2 * H_ : H_;
    const int n0 = blockIdx.x * 32, k0 = blockIdx.y * 32;
    if (n0 >= N) return;
    __shared__ float ts[32][33];
    const int tx = threadIdx.x, ty = threadIdx.y;
#pragma unroll
    for (int i = 0; i < 4; i++)
        ts[ty + 8 * i][tx] = W[(size_t)(k0 + ty + 8 * i) * N + n0 + tx];
    __syncthreads();
#pragma unroll
    for (int i = 0; i < 4; i++)
        T[(size_t)(n0 + ty + 8 * i) * H_ + k0 + tx] = __float2half_rn(ts[tx][ty + 8 * i]);
}

// ---------------- fp16 GEMM: CTA 128x128, K-tile 64, 8 warps 2x4 ----------------
// A[M,K], B[N,K] half, K-major. smem 128B rows, GSW swizzle. 2 stages.
#define GSTG 32768                 // A 16KB + B 16KB
#define GS_SMEM (2 * GSTG)         // 65536

__global__ __launch_bounds__(256, 2) void gemm_h(
    const __half* __restrict__ A, const __half* __restrict__ Bm,
    void* __restrict__ Cv, int M, int N, int K, int outHalf, float outScale)
{
    extern __shared__ char smem[];
    const uint32_t sb = smem_u32(smem);
    const int tid = threadIdx.x, lane = tid & 31, wid = tid >> 5;
    const int bm = blockIdx.y * 128, bn = blockIdx.x * 128;
    const int wm = (wid & 1) * 64, wn = (wid >> 1) * 32;

    // loads: 2 threads/row, 4x16B chunks each
    const int lrow = tid >> 1, lc0 = (tid & 1) * 4;
    const __half* Ag = A + (size_t)(bm + lrow) * K + lc0 * 8;
    const __half* Bg = Bm + (size_t)(bn + lrow) * K + lc0 * 8;
    uint32_t sdst[4];
#pragma unroll
    for (int c = 0; c < 4; c++) sdst[c] = GSW(lrow * 128 + (lc0 + c) * 16);

    // fragment lane pieces
    const uint32_t aRow = wm + (lane & 7) + ((lane >> 3) & 1) * 8;
    const uint32_t aKb  = ((lane >> 4) & 1) * 16;
    const uint32_t bRow = wn + (lane & 7) + ((lane >> 4) & 1) * 8;
    const uint32_t bKb  = ((lane >> 3) & 1) * 16;

    float acc[4][4][4];
#pragma unroll
    for (int i = 0; i < 4; i++)
#pragma unroll
        for (int j = 0; j < 4; j++)
#pragma unroll
            for (int r = 0; r < 4; r++) acc[i][j][r] = 0.0f;

    const int NT = K / 64;

    // prologue
#pragma unroll
    for (int c = 0; c < 4; c++) {
        cp16(smem + sdst[c], Ag + c * 8);
        cp16(smem + 16384 + sdst[c], Bg + c * 8);
    }
    asm volatile("cp.async.commit_group;");

    for (int t = 0; t < NT; t++) {
        asm volatile("cp.async.wait_group 0;");
        __syncthreads();
        if (t + 1 < NT) {
            char* sd = smem + ((t + 1) & 1) * GSTG;
            const int k0 = (t + 1) * 64;
#pragma unroll
            for (int c = 0; c < 4; c++) {
                cp16(sd + sdst[c], Ag + k0 + c * 8);
                cp16(sd + 16384 + sdst[c], Bg + k0 + c * 8);
            }
            asm volatile("cp.async.commit_group;");
        }

        const uint32_t sA = sb + (t & 1) * GSTG;
        const uint32_t sB = sA + 16384;
#pragma unroll
        for (int ks = 0; ks < 4; ks++) {
            uint32_t af[4][4], bf[2][4];
#pragma unroll
            for (int im = 0; im < 4; im++)
                ldsm4(af[im], sA + GSW((aRow + im * 16) * 128 + ks * 32 + aKb));
#pragma unroll
            for (int jp = 0; jp < 2; jp++)
                ldsm4(bf[jp], sB + GSW((bRow + jp * 16) * 128 + ks * 32 + bKb));
#pragma unroll
            for (int im = 0; im < 4; im++)
#pragma unroll
                for (int jn = 0; jn < 4; jn++) {
                    const uint32_t* bb = bf[jn >> 1];
                    const int sx = (jn & 1) * 2;
                    mma_f16(acc[im][jn], af[im], bb[sx], bb[sx + 1]);
                }
        }
        __syncthreads();
    }

    const int er = lane >> 2, ec = 2 * (lane & 3);
#pragma unroll
    for (int im = 0; im < 4; im++)
#pragma unroll
        for (int jn = 0; jn < 4; jn++) {
            const int row = bm + wm + im * 16 + er;
            const int col = bn + wn + jn * 8 + ec;
            const float v0 = acc[im][jn][0] * outScale, v1 = acc[im][jn][1] * outScale;
            const float v2 = acc[im][jn][2] * outScale, v3 = acc[im][jn][3] * outScale;
            if (outHalf) {
                __half* C = (__half*)Cv;
                *(__half2*)&C[(size_t)row * N + col] = __floats2half2_rn(v0, v1);
                *(__half2*)&C[(size_t)(row + 8) * N + col] = __floats2half2_rn(v2, v3);
            } else {
                float* C = (float*)Cv;
                *(float2*)&C[(size_t)row * N + col] = make_float2(v0, v1);
                *(float2*)&C[(size_t)(row + 8) * N + col] = make_float2(v2, v3);
            }
        }
}

// ---------------- dual-branch flash attention, fp16 ----------------
// CTA: 128 queries, 8 warps x 16 q-rows. K/V tiles [64 key][64d=128B] per stage
// (V read transposed via ldmatrix.trans). P [128 q][64k=128B].
#define ASTG 16384                  // K 8KB + V 8KB
#define AT_P 32768
#define ATTN_SMEM (AT_P + 16384)    // 49152

__global__ __launch_bounds__(256, 2) void attn_h(
    const __half* __restrict__ Q, const __half* __restrict__ KVs,
    const __half* __restrict__ KVl, __half* __restrict__ Out,
    const float* __restrict__ p_mixw, const float* __restrict__ p_decay)
{
    extern __shared__ char smem[];
    const uint32_t sb = smem_u32(smem);
    const int tid = threadIdx.x, lane = tid & 31, wid = tid >> 5;
    const int g = lane >> 2, tg = lane & 3;
    const int q0 = blockIdx.x * 128;
    const int h = blockIdx.y, b = blockIdx.z;
    const int mw = wid * 16;

    const float alpha   = 1.0f / (1.0f + __expf(-p_mixw[0]));
    const float lambda2 = (1.0f - p_decay[0]) * LOG2E;
    const float wmix[2] = {alpha, 1.0f - alpha};

    // fragment lane pieces
    const uint32_t bRow = (lane & 7) + ((lane >> 4) & 1) * 8;   // B (K): n=key row
    const uint32_t bKb  = ((lane >> 3) & 1) * 16;               // B (K): k=dim bytes
    const uint32_t pRow = mw + (lane & 7) + ((lane >> 3) & 1) * 8;  // A (P)
    const uint32_t pKb  = ((lane >> 4) & 1) * 16;
    const uint32_t vRow = (lane & 7) + ((lane >> 3) & 1) * 8;   // V trans: key row
    const uint32_t vKb  = ((lane >> 4) & 1) * 16;               // V trans: d bytes

    // Q fragments in registers (pre-scaled in GEMM epilogue)
    uint32_t qa[4][4];
    {
        const __half* r0 = Q + ((size_t)(b * L_ + q0 + mw + g)) * H_ + h * HD_;
        const __half* r1 = r0 + (size_t)8 * H_;
#pragma unroll
        for (int ks = 0; ks < 4; ks++) {
            qa[ks][0] = *(const uint32_t*)(r0 + ks * 16 + 2 * tg);
            qa[ks][1] = *(const uint32_t*)(r1 + ks * 16 + 2 * tg);
            qa[ks][2] = *(const uint32_t*)(r0 + ks * 16 + 8 + 2 * tg);
            qa[ks][3] = *(const uint32_t*)(r1 + ks * 16 + 8 + 2 * tg);
        }
    }

    // tile loads: 4 threads/row, 2x16B chunks each for K and V
    const int kr = tid >> 2, c0 = tid & 3;

    auto issue_load = [&](int slot) {
        const int br = slot >> 4, tt = slot & 15;
        const __half* Kb = (br ? KVl : KVs) +
            ((size_t)(b * L_ + tt * 64 + kr)) * (2 * H_) + h * HD_;
        const __half* Vb = Kb + H_;
        char* stg = smem + (slot & 1) * ASTG;
#pragma unroll
        for (int c = 0; c < 2; c++) {
            const int ch = c0 + c * 4;
            const uint32_t d = GSW(kr * 128 + ch * 16);
            cp16(stg + d, Kb + ch * 8);
            cp16(stg + 8192 + d, Vb + ch * 8);
        }
        asm volatile("cp.async.commit_group;");
    };

    issue_load(0);

    for (int branch = 0; branch < 2; branch++) {
        float l0 = 0.0f, l1 = 0.0f;
        float o[8][4];
#pragma unroll
        for (int jn = 0; jn < 8; jn++)
#pragma unroll
            for (int r = 0; r < 4; r++) o[jn][r] = 0.0f;

        for (int t = 0; t < 16; t++) {
            const int slot = branch * 16 + t;
            asm volatile("cp.async.wait_group 0;");
            __syncthreads();
            if (slot + 1 < 32) issue_load(slot + 1);

            const uint32_t stK = sb + (slot & 1) * ASTG;
            const uint32_t stV = stK + 8192;

            // ---- S = Q K^T (4 ksteps of 16 dims) ----
            float s[8][4];
#pragma unroll
            for (int jn = 0; jn < 8; jn++)
#pragma unroll
                for (int r = 0; r < 4; r++) s[jn][r] = 0.0f;
#pragma unroll
            for (int ks = 0; ks < 4; ks++) {
                uint32_t bf[4][4];
#pragma unroll
                for (int jp = 0; jp < 4; jp++)
                    ldsm4(bf[jp], stK + GSW((bRow + jp * 16) * 128 + ks * 32 + bKb));
#pragma unroll
                for (int jn = 0; jn < 8; jn++) {
                    const uint32_t* bb = bf[jn >> 1];
                    const int sx = (jn & 1) * 2;
                    mma_f16(s[jn], qa[ks], bb[sx], bb[sx + 1]);
                }
            }

            if (branch == 0) {
                const float r0 = (float)(q0 + mw + g), r1 = r0 + 8.0f;
#pragma unroll
                for (int jn = 0; jn < 8; jn++) {
                    const float cA = (float)(t * 64 + jn * 8 + 2 * tg), cB = cA + 1.0f;
                    s[jn][0] -= fabsf(r0 - cA) * lambda2;
                    s[jn][1] -= fabsf(r0 - cB) * lambda2;
                    s[jn][2] -= fabsf(r1 - cA) * lambda2;
                    s[jn][3] -= fabsf(r1 - cB) * lambda2;
                }
            }

            // ---- p = exp2(s - 12); lane-local l; store P (half2, swizzled) ----
#pragma unroll
            for (int jn = 0; jn < 8; jn++) {
                const float p0 = ex2(s[jn][0] - 12.0f);
                const float p1 = ex2(s[jn][1] - 12.0f);
                const float p2 = ex2(s[jn][2] - 12.0f);
                const float p3 = ex2(s[jn][3] - 12.0f);
                l0 += p0 + p1; l1 += p2 + p3;
                const uint32_t cOff = jn * 16 + 4 * tg;
                *(__half2*)(smem + AT_P + GSW((mw + g) * 128 + cOff)) =
                    __floats2half2_rn(p0, p1);
                *(__half2*)(smem + AT_P + GSW((mw + g + 8) * 128 + cOff)) =
                    __floats2half2_rn(p2, p3);
            }
            __syncwarp();   // P rows are warp-private

            // ---- O += P V (V via ldmatrix.trans from [key][d] tile) ----
#pragma unroll
            for (int ks = 0; ks < 4; ks++) {
                uint32_t pf[4], vf[4][4];
                ldsm4(pf, sb + AT_P + GSW(pRow * 128 + ks * 32 + pKb));
#pragma unroll
                for (int jp = 0; jp < 4; jp++)
                    ldsm4t(vf[jp], stV + GSW((ks * 16 + vRow) * 128 + jp * 32 + vKb));
#pragma unroll
                for (int jn = 0; jn < 8; jn++) {
                    const uint32_t* bb = vf[jn >> 1];
                    const int sx = (jn & 1) * 2;
                    mma_f16(o[jn], pf, bb[sx], bb[sx + 1]);
                }
            }
        }

        l0 += __shfl_xor_sync(0xffffffffu, l0, 1);
        l0 += __shfl_xor_sync(0xffffffffu, l0, 2);
        l1 += __shfl_xor_sync(0xffffffffu, l1, 1);
        l1 += __shfl_xor_sync(0xffffffffu, l1, 2);

        const float w  = wmix[branch];
        const float i0 = w / l0, i1 = w / l1;
        __half* ob = Out + ((size_t)(b * L_ + q0 + mw + g)) * H_ + h * HD_;
        if (branch == 0) {
#pragma unroll
            for (int jn = 0; jn < 8; jn++) {
                const int col = jn * 8 + 2 * tg;
                *(__half2*)(ob + col) = __floats2half2_rn(o[jn][0] * i0, o[jn][1] * i0);
                *(__half2*)(ob + 8 * H_ + col) = __floats2half2_rn(o[jn][2] * i1, o[jn][3] * i1);
            }
        } else {
#pragma unroll
            for (int jn = 0; jn < 8; jn++) {
                const int col = jn * 8 + 2 * tg;
                float2 u0 = __half22float2(*(__half2*)(ob + col));
                float2 u1 = __half22float2(*(__half2*)(ob + 8 * H_ + col));
                *(__half2*)(ob + col) =
                    __floats2half2_rn(u0.x + o[jn][0] * i0, u0.y + o[jn][1] * i0);
                *(__half2*)(ob + 8 * H_ + col) =
                    __floats2half2_rn(u1.x + o[jn][2] * i1, u1.y + o[jn][3] * i1);
            }
        }
    }
}

// ---------------------------------------------------------------------------
extern "C" void kernel_launch(void* const* d_in, const int* in_sizes, int n_in,
                              void* d_out, int out_size)
{
    const float* x     = (const float*)d_in[0];
    const float* Wq    = (const float*)d_in[1];
    const float* Wkvs  = (const float*)d_in[2];
    const float* Wkvl  = (const float*)d_in[3];
    const float* Wo    = (const float*)d_in[4];
    const float* mixw  = (const float*)d_in[5];
    const float* decay = (const float*)d_in[6];
    float* out = (float*)d_out;

    __half *xh, *qh, *kvsh, *kvlh, *mixh, *wqh, *wsh, *wlh, *woh;
    cudaGetSymbolAddress((void**)&xh,   g_xh);
    cudaGetSymbolAddress((void**)&qh,   g_Qh);
    cudaGetSymbolAddress((void**)&kvsh, g_KVsh);
    cudaGetSymbolAddress((void**)&kvlh, g_KVlh);
    cudaGetSymbolAddress((void**)&mixh, g_mixh);
    cudaGetSymbolAddress((void**)&wqh,  g_Wqth);
    cudaGetSymbolAddress((void**)&wsh,  g_Wsth);
    cudaGetSymbolAddress((void**)&wlh,  g_Wlth);
    cudaGetSymbolAddress((void**)&woh,  g_Woth);

    cudaFuncSetAttribute(gemm_h,
                         cudaFuncAttributeMaxDynamicSharedMemorySize, GS_SMEM);
    cudaFuncSetAttribute(attn_h,
                         cudaFuncAttributeMaxDynamicSharedMemorySize, ATTN_SMEM);

    const float QSCALE = 0.125f * LOG2E;

    // preprocess
    to_half<<<M_ * H_ / 4 / 256, 256>>>(x, xh, M_ * H_ / 4);
    wtrans_h<<<dim3(2 * H_ / 32, H_ / 32, 4), dim3(32, 8)>>>(Wq, Wkvs, Wkvl, Wo,
                                                             wqh, wsh, wlh, woh);

    // projections (half outputs; Q pre-scaled)
    gemm_h<<<dim3(H_ / 128,     M_ / 128), 256, GS_SMEM>>>(xh, wqh, qh,   M_, H_,     H_, 1, QSCALE);
    gemm_h<<<dim3(2 * H_ / 128, M_ / 128), 256, GS_SMEM>>>(xh, wsh, kvsh, M_, 2 * H_, H_, 1, 1.0f);
    gemm_h<<<dim3(2 * H_ / 128, M_ / 128), 256, GS_SMEM>>>(xh, wlh, kvlh, M_, 2 * H_, H_, 1, 1.0f);

    // attention (reads K and V straight from KV halves; V transposed via ldsm.trans)
    attn_h<<<dim3(L_ / 128, NH_, B_), 256, ATTN_SMEM>>>(qh, kvsh, kvlh, mixh, mixw, decay);

    // output projection (fp32 out)
    gemm_h<<<dim3(H_ / 128, M_ / 128), 256, GS_SMEM>>>(mixh, woh, out, M_, H_, H_, 0, 1.0f);
}

// round 10
// speedup vs baseline: 2.6074x; 1.1152x over previous
#include <cuda_runtime.h>
#include <cuda_fp16.h>
#include <cstdint>

#define B_  4
#define L_  1024
#define H_  1024
#define NH_ 16
#define HD_ 64
#define M_  (B_*L_)   // 4096
#define NP_ (5 * H_)  // fused projection width 5120
#define LOG2E 1.4426950408889634f

// ---------------- scratch ----------------
__device__ __half g_xh  [M_ * H_];
__device__ __half g_proj[M_ * NP_];      // [Q(scaled) | Ks | Vs | Kl | Vl]
__device__ __half g_mixh[M_ * H_];
__device__ __half g_Wall[NP_ * H_];      // [Wq^T*qs ; Wkvs^T ; Wkvl^T]
__device__ __half g_Woth[H_ * H_];

// ---------------- PTX helpers ----------------
__device__ __forceinline__ float ex2(float x) {
    float y; asm("ex2.approx.ftz.f32 %0, %1;" : "=f"(y) : "f"(x)); return y;
}
__device__ __forceinline__ void mma_f16(float* d, const uint32_t* a,
                                        uint32_t b0, uint32_t b1) {
    asm volatile(
        "mma.sync.aligned.m16n8k16.row.col.f32.f16.f16.f32 "
        "{%0,%1,%2,%3}, {%4,%5,%6,%7}, {%8,%9}, {%0,%1,%2,%3};"
        : "+f"(d[0]), "+f"(d[1]), "+f"(d[2]), "+f"(d[3])
        : "r"(a[0]), "r"(a[1]), "r"(a[2]), "r"(a[3]), "r"(b0), "r"(b1));
}
__device__ __forceinline__ void ldsm4(uint32_t* r, uint32_t addr) {
    asm volatile("ldmatrix.sync.aligned.m8n8.x4.shared.b16 {%0,%1,%2,%3}, [%4];"
        : "=r"(r[0]), "=r"(r[1]), "=r"(r[2]), "=r"(r[3]) : "r"(addr));
}
__device__ __forceinline__ void ldsm4t(uint32_t* r, uint32_t addr) {
    asm volatile("ldmatrix.sync.aligned.m8n8.x4.trans.shared.b16 {%0,%1,%2,%3}, [%4];"
        : "=r"(r[0]), "=r"(r[1]), "=r"(r[2]), "=r"(r[3]) : "r"(addr));
}
__device__ __forceinline__ void cp16(void* smem_dst, const void* gmem_src) {
    unsigned s = (unsigned)__cvta_generic_to_shared(smem_dst);
    asm volatile("cp.async.cg.shared.global [%0], [%1], 16;" :: "r"(s), "l"(gmem_src));
}
__device__ __forceinline__ uint32_t smem_u32(const void* p) {
    uint32_t a;
    asm("{ .reg .u64 t; cvta.to.shared.u64 t, %1; cvt.u32.u64 %0, t; }" : "=r"(a) : "l"(p));
    return a;
}
__device__ __forceinline__ uint32_t packh2(float a, float b) {
    uint32_t r;
    asm("cvt.rn.f16x2.f32 %0, %2, %1;" : "=r"(r) : "f"(a), "f"(b));
    return r;
}
#define GSW(o) ((o) ^ (((o) >> 3) & 0x70))

// ---------------- preprocessing ----------------
__global__ __launch_bounds__(256) void to_half(
    const float* __restrict__ src, __half* __restrict__ dst, int n4)
{
    int i = blockIdx.x * blockDim.x + threadIdx.x;
    if (i >= n4) return;
    float4 v = ((const float4*)src)[i];
    ((__half2*)dst)[2 * i]     = __floats2half2_rn(v.x, v.y);
    ((__half2*)dst)[2 * i + 1] = __floats2half2_rn(v.z, v.w);
}

// weights -> g_Wall rows [0:1024)=Wq^T*QSCALE, [1024:3072)=Wkvs^T, [3072:5120)=Wkvl^T
// z=3 -> g_Woth = Wo^T
__global__ __launch_bounds__(256) void wtrans_h(
    const float* __restrict__ Wq, const float* __restrict__ Ws,
    const float* __restrict__ Wl, const float* __restrict__ Wo,
    __half* __restrict__ Wall, __half* __restrict__ To)
{
    const int z = blockIdx.z;
    const float* W = (z == 0) ? Wq : (z == 1) ? Ws : (z == 2) ? Wl : Wo;
    const int N = (z == 1 || z == 2) ? 2 * H_ : H_;
    const int rowOff = (z == 0) ? 0 : (z == 1) ? H_ : (z == 2) ? 3 * H_ : 0;
    const float sc = (z == 0) ? 0.125f * LOG2E : 1.0f;
    __half* T = (z == 3) ? To : (Wall + (size_t)rowOff * H_);
    const int n0 = blockIdx.x * 32, k0 = blockIdx.y * 32;
    if (n0 >= N) return;
    __shared__ float ts[32][33];
    const int tx = threadIdx.x, ty = threadIdx.y;
#pragma unroll
    for (int i = 0; i < 4; i++)
        ts[ty + 8 * i][tx] = W[(size_t)(k0 + ty + 8 * i) * N + n0 + tx];
    __syncthreads();
#pragma unroll
    for (int i = 0; i < 4; i++)
        T[(size_t)(n0 + ty + 8 * i) * H_ + k0 + tx] = __float2half_rn(ts[tx][ty + 8 * i] * sc);
}

// ---------------- fp16 GEMM: CTA 128x128, K-tile 64, 8 warps 2x4 ----------------
#define GSTG 32768
#define GS_SMEM (2 * GSTG)

__global__ __launch_bounds__(256, 2) void gemm_h(
    const __half* __restrict__ A, const __half* __restrict__ Bm,
    void* __restrict__ Cv, int M, int N, int K, int outHalf)
{
    extern __shared__ char smem[];
    const uint32_t sb = smem_u32(smem);
    const int tid = threadIdx.x, lane = tid & 31, wid = tid >> 5;
    const int bm = blockIdx.y * 128, bn = blockIdx.x * 128;
    const int wm = (wid & 1) * 64, wn = (wid >> 1) * 32;

    const int lrow = tid >> 1, lc0 = (tid & 1) * 4;
    const __half* Ag = A + (size_t)(bm + lrow) * K + lc0 * 8;
    const __half* Bg = Bm + (size_t)(bn + lrow) * K + lc0 * 8;
    uint32_t sdst[4];
#pragma unroll
    for (int c = 0; c < 4; c++) sdst[c] = GSW(lrow * 128 + (lc0 + c) * 16);

    const uint32_t aRow = wm + (lane & 7) + ((lane >> 3) & 1) * 8;
    const uint32_t aKb  = ((lane >> 4) & 1) * 16;
    const uint32_t bRow = wn + (lane & 7) + ((lane >> 4) & 1) * 8;
    const uint32_t bKb  = ((lane >> 3) & 1) * 16;

    float acc[4][4][4];
#pragma unroll
    for (int i = 0; i < 4; i++)
#pragma unroll
        for (int j = 0; j < 4; j++)
#pragma unroll
            for (int r = 0; r < 4; r++) acc[i][j][r] = 0.0f;

    const int NT = K / 64;
#pragma unroll
    for (int c = 0; c < 4; c++) {
        cp16(smem + sdst[c], Ag + c * 8);
        cp16(smem + 16384 + sdst[c], Bg + c * 8);
    }
    asm volatile("cp.async.commit_group;");

    for (int t = 0; t < NT; t++) {
        asm volatile("cp.async.wait_group 0;");
        __syncthreads();
        if (t + 1 < NT) {
            char* sd = smem + ((t + 1) & 1) * GSTG;
            const int k0 = (t + 1) * 64;
#pragma unroll
            for (int c = 0; c < 4; c++) {
                cp16(sd + sdst[c], Ag + k0 + c * 8);
                cp16(sd + 16384 + sdst[c], Bg + k0 + c * 8);
            }
            asm volatile("cp.async.commit_group;");
        }

        const uint32_t sA = sb + (t & 1) * GSTG;
        const uint32_t sB = sA + 16384;
#pragma unroll
        for (int ks = 0; ks < 4; ks++) {
            uint32_t af[4][4], bf[2][4];
#pragma unroll
            for (int im = 0; im < 4; im++)
                ldsm4(af[im], sA + GSW((aRow + im * 16) * 128 + ks * 32 + aKb));
#pragma unroll
            for (int jp = 0; jp < 2; jp++)
                ldsm4(bf[jp], sB + GSW((bRow + jp * 16) * 128 + ks * 32 + bKb));
#pragma unroll
            for (int im = 0; im < 4; im++)
#pragma unroll
                for (int jn = 0; jn < 4; jn++) {
                    const uint32_t* bb = bf[jn >> 1];
                    const int sx = (jn & 1) * 2;
                    mma_f16(acc[im][jn], af[im], bb[sx], bb[sx + 1]);
                }
        }
        // no bottom barrier — top-of-loop barrier orders reads before the
        // next iteration's cp.async writes into this stage.
    }

    const int er = lane >> 2, ec = 2 * (lane & 3);
#pragma unroll
    for (int im = 0; im < 4; im++)
#pragma unroll
        for (int jn = 0; jn < 4; jn++) {
            const int row = bm + wm + im * 16 + er;
            const int col = bn + wn + jn * 8 + ec;
            if (outHalf) {
                __half* C = (__half*)Cv;
                *(__half2*)&C[(size_t)row * N + col] =
                    __floats2half2_rn(acc[im][jn][0], acc[im][jn][1]);
                *(__half2*)&C[(size_t)(row + 8) * N + col] =
                    __floats2half2_rn(acc[im][jn][2], acc[im][jn][3]);
            } else {
                float* C = (float*)Cv;
                *(float2*)&C[(size_t)row * N + col] =
                    make_float2(acc[im][jn][0], acc[im][jn][1]);
                *(float2*)&C[(size_t)(row + 8) * N + col] =
                    make_float2(acc[im][jn][2], acc[im][jn][3]);
            }
        }
}

// ---------------- dual-branch flash attention, fp16, P in registers ----------------
// CTA: 128 queries, 8 warps x 16 q-rows. K/V tiles [64 key][64d=128B] per stage.
#define ASTG 16384                  // K 8KB + V 8KB
#define ATTN_SMEM (2 * ASTG)        // 32768

__global__ __launch_bounds__(256, 2) void attn_h(
    const __half* __restrict__ Proj, __half* __restrict__ Out,
    const float* __restrict__ p_mixw, const float* __restrict__ p_decay)
{
    extern __shared__ char smem[];
    const uint32_t sb = smem_u32(smem);
    const int tid = threadIdx.x, lane = tid & 31, wid = tid >> 5;
    const int g = lane >> 2, tg = lane & 3;
    const int q0 = blockIdx.x * 128;
    const int h = blockIdx.y, b = blockIdx.z;
    const int mw = wid * 16;

    const float alpha   = 1.0f / (1.0f + __expf(-p_mixw[0]));
    const float lambda2 = (1.0f - p_decay[0]) * LOG2E;
    const float wmix[2] = {alpha, 1.0f - alpha};

    const uint32_t bRow = (lane & 7) + ((lane >> 4) & 1) * 8;   // K frags: key row
    const uint32_t bKb  = ((lane >> 3) & 1) * 16;
    const uint32_t vRow = (lane & 7) + ((lane >> 3) & 1) * 8;   // V trans: key row
    const uint32_t vKb  = ((lane >> 4) & 1) * 16;

    // Q fragments (pre-scaled via folded weights)
    uint32_t qa[4][4];
    {
        const __half* r0 = Proj + ((size_t)(b * L_ + q0 + mw + g)) * NP_ + h * HD_;
        const __half* r1 = r0 + (size_t)8 * NP_;
#pragma unroll
        for (int ks = 0; ks < 4; ks++) {
            qa[ks][0] = *(const uint32_t*)(r0 + ks * 16 + 2 * tg);
            qa[ks][1] = *(const uint32_t*)(r1 + ks * 16 + 2 * tg);
            qa[ks][2] = *(const uint32_t*)(r0 + ks * 16 + 8 + 2 * tg);
            qa[ks][3] = *(const uint32_t*)(r1 + ks * 16 + 8 + 2 * tg);
        }
    }

    const int kr = tid >> 2, c0 = tid & 3;

    auto issue_load = [&](int slot) {
        const int br = slot >> 4, tt = slot & 15;
        const __half* Kb = Proj + ((size_t)(b * L_ + tt * 64 + kr)) * NP_ +
                           (H_ + br * 2 * H_) + h * HD_;
        const __half* Vb = Kb + H_;
        char* stg = smem + (slot & 1) * ASTG;
#pragma unroll
        for (int c = 0; c < 2; c++) {
            const int ch = c0 + c * 4;
            const uint32_t d = GSW(kr * 128 + ch * 16);
            cp16(stg + d, Kb + ch * 8);
            cp16(stg + 8192 + d, Vb + ch * 8);
        }
        asm volatile("cp.async.commit_group;");
    };

    issue_load(0);

    for (int branch = 0; branch < 2; branch++) {
        float l0 = 0.0f, l1 = 0.0f;
        float o[8][4];
#pragma unroll
        for (int jn = 0; jn < 8; jn++)
#pragma unroll
            for (int r = 0; r < 4; r++) o[jn][r] = 0.0f;

        for (int t = 0; t < 16; t++) {
            const int slot = branch * 16 + t;
            asm volatile("cp.async.wait_group 0;");
            __syncthreads();
            if (slot + 1 < 32) issue_load(slot + 1);

            const uint32_t stK = sb + (slot & 1) * ASTG;
            const uint32_t stV = stK + 8192;

            // ---- S = Q K^T ----
            float s[8][4];
#pragma unroll
            for (int jn = 0; jn < 8; jn++)
#pragma unroll
                for (int r = 0; r < 4; r++) s[jn][r] = 0.0f;
#pragma unroll
            for (int ks = 0; ks < 4; ks++) {
                uint32_t bf[4][4];
#pragma unroll
                for (int jp = 0; jp < 4; jp++)
                    ldsm4(bf[jp], stK + GSW((bRow + jp * 16) * 128 + ks * 32 + bKb));
#pragma unroll
                for (int jn = 0; jn < 8; jn++) {
                    const uint32_t* bb = bf[jn >> 1];
                    const int sx = (jn & 1) * 2;
                    mma_f16(s[jn], qa[ks], bb[sx], bb[sx + 1]);
                }
            }

            if (branch == 0) {
                const float r0 = (float)(q0 + mw + g), r1 = r0 + 8.0f;
#pragma unroll
                for (int jn = 0; jn < 8; jn++) {
                    const float cA = (float)(t * 64 + jn * 8 + 2 * tg), cB = cA + 1.0f;
                    s[jn][0] -= fabsf(r0 - cA) * lambda2;
                    s[jn][1] -= fabsf(r0 - cB) * lambda2;
                    s[jn][2] -= fabsf(r1 - cA) * lambda2;
                    s[jn][3] -= fabsf(r1 - cB) * lambda2;
                }
            }

            // ---- p = exp2(s - 12): stays in registers as PV A-fragments ----
            uint32_t pf[4][4];   // [kchunk][frag]
#pragma unroll
            for (int jn = 0; jn < 8; jn++) {
                const float p0 = ex2(s[jn][0] - 12.0f);
                const float p1 = ex2(s[jn][1] - 12.0f);
                const float p2 = ex2(s[jn][2] - 12.0f);
                const float p3 = ex2(s[jn][3] - 12.0f);
                l0 += p0 + p1; l1 += p2 + p3;
                const int kc = jn >> 1, half = (jn & 1) * 2;
                pf[kc][half + 0] = packh2(p0, p1);
                pf[kc][half + 1] = packh2(p2, p3);
            }

            // ---- O += P V (V via ldmatrix.trans from [key][d] tile) ----
#pragma unroll
            for (int ks = 0; ks < 4; ks++) {
                uint32_t vf[4][4];
#pragma unroll
                for (int jp = 0; jp < 4; jp++)
                    ldsm4t(vf[jp], stV + GSW((ks * 16 + vRow) * 128 + jp * 32 + vKb));
#pragma unroll
                for (int jn = 0; jn < 8; jn++) {
                    const uint32_t* bb = vf[jn >> 1];
                    const int sx = (jn & 1) * 2;
                    mma_f16(o[jn], pf[ks], bb[sx], bb[sx + 1]);
                }
            }
        }

        l0 += __shfl_xor_sync(0xffffffffu, l0, 1);
        l0 += __shfl_xor_sync(0xffffffffu, l0, 2);
        l1 += __shfl_xor_sync(0xffffffffu, l1, 1);
        l1 += __shfl_xor_sync(0xffffffffu, l1, 2);

        const float w  = wmix[branch];
        const float i0 = w / l0, i1 = w / l1;
        __half* ob = Out + ((size_t)(b * L_ + q0 + mw + g)) * H_ + h * HD_;
        if (branch == 0) {
#pragma unroll
            for (int jn = 0; jn < 8; jn++) {
                const int col = jn * 8 + 2 * tg;
                *(__half2*)(ob + col) = __floats2half2_rn(o[jn][0] * i0, o[jn][1] * i0);
                *(__half2*)(ob + 8 * H_ + col) = __floats2half2_rn(o[jn][2] * i1, o[jn][3] * i1);
            }
        } else {
#pragma unroll
            for (int jn = 0; jn < 8; jn++) {
                const int col = jn * 8 + 2 * tg;
                float2 u0 = __half22float2(*(__half2*)(ob + col));
                float2 u1 = __half22float2(*(__half2*)(ob + 8 * H_ + col));
                *(__half2*)(ob + col) =
                    __floats2half2_rn(u0.x + o[jn][0] * i0, u0.y + o[jn][1] * i0);
                *(__half2*)(ob + 8 * H_ + col) =
                    __floats2half2_rn(u1.x + o[jn][2] * i1, u1.y + o[jn][3] * i1);
            }
        }
    }
}

// ---------------------------------------------------------------------------
extern "C" void kernel_launch(void* const* d_in, const int* in_sizes, int n_in,
                              void* d_out, int out_size)
{
    const float* x     = (const float*)d_in[0];
    const float* Wq    = (const float*)d_in[1];
    const float* Wkvs  = (const float*)d_in[2];
    const float* Wkvl  = (const float*)d_in[3];
    const float* Wo    = (const float*)d_in[4];
    const float* mixw  = (const float*)d_in[5];
    const float* decay = (const float*)d_in[6];
    float* out = (float*)d_out;

    __half *xh, *proj, *mixh, *wall, *woh;
    cudaGetSymbolAddress((void**)&xh,   g_xh);
    cudaGetSymbolAddress((void**)&proj, g_proj);
    cudaGetSymbolAddress((void**)&mixh, g_mixh);
    cudaGetSymbolAddress((void**)&wall, g_Wall);
    cudaGetSymbolAddress((void**)&woh,  g_Woth);

    cudaFuncSetAttribute(gemm_h,
                         cudaFuncAttributeMaxDynamicSharedMemorySize, GS_SMEM);
    cudaFuncSetAttribute(attn_h,
                         cudaFuncAttributeMaxDynamicSharedMemorySize, ATTN_SMEM);

    // preprocess
    to_half<<<M_ * H_ / 4 / 256, 256>>>(x, xh, M_ * H_ / 4);
    wtrans_h<<<dim3(2 * H_ / 32, H_ / 32, 4), dim3(32, 8)>>>(Wq, Wkvs, Wkvl, Wo,
                                                             wall, woh);

    // fused projections: proj[M, 5120]
    gemm_h<<<dim3(NP_ / 128, M_ / 128), 256, GS_SMEM>>>(xh, wall, proj, M_, NP_, H_, 1);

    // attention
    attn_h<<<dim3(L_ / 128, NH_, B_), 256, ATTN_SMEM>>>(proj, mixh, mixw, decay);

    // output projection (fp32 out)
    gemm_h<<<dim3(H_ / 128, M_ / 128), 256, GS_SMEM>>>(mixh, woh, out, M_, H_, H_, 0);
}